// round 10
// baseline (speedup 1.0000x reference)
#include <cuda_runtime.h>
#include <cuda_bf16.h>
#include <math.h>

#define NN      10000
#define EE      100000
#define INC     64
#define ED      16
#define HIDD    128
#define NHEADS  4
#define HCC     512
#define NLAYERS 4
#define NG      256

// ---------------- scratch (device globals; no allocation allowed) ----------------
__device__ float g_h0[NN * HIDD];
__device__ float g_xl[NN * HCC];
__device__ float g_xr[NN * HCC];
__device__ float g_res[NN * HIDD];
__device__ int   g_deg[NN];
__device__ int   g_cur[NN];
__device__ int   g_off[NN + 1];
__device__ int   g_csr[EE];
__device__ float g_pool[NG * HIDD];
__device__ float g_cnt[NG];

// packed bf16x2 (hi/lo split) buffers: activations ping-pong + weights
__device__ unsigned g_PAh[NN * 64], g_PAl[NN * 64];
__device__ unsigned g_PBh[NN * 64], g_PBl[NN * 64];
__device__ unsigned g_WinH[32 * 128],          g_WinL[32 * 128];
__device__ unsigned g_WlH[NLAYERS * 64 * HCC], g_WlL[NLAYERS * 64 * HCC];
__device__ unsigned g_WrH[NLAYERS * 64 * HCC], g_WrL[NLAYERS * 64 * HCC];
__device__ unsigned g_WresH[3 * 64 * HIDD],    g_WresL[3 * 64 * HIDD];

__device__ __forceinline__ float eluf(float v) { return v > 0.f ? v : expm1f(v); }

// split a,b (adjacent k / adjacent cols) into packed bf16x2 hi and lo words
__device__ __forceinline__ void packHL(float a, float b, unsigned& hi, unsigned& lo) {
    __nv_bfloat16 ha = __float2bfloat16(a);
    __nv_bfloat16 hb = __float2bfloat16(b);
    float la = a - __bfloat162float(ha);
    float lb = b - __bfloat162float(hb);
    __nv_bfloat16 lA = __float2bfloat16(la);
    __nv_bfloat16 lB = __float2bfloat16(lb);
    __nv_bfloat162 h2 = __halves2bfloat162(ha, hb);
    __nv_bfloat162 l2 = __halves2bfloat162(lA, lB);
    hi = *reinterpret_cast<unsigned*>(&h2);
    lo = *reinterpret_cast<unsigned*>(&l2);
}

#define MMA_BF16(cc, aa, b0r, b1r) \
    asm("mma.sync.aligned.m16n8k16.row.col.f32.bf16.bf16.f32 " \
        "{%0,%1,%2,%3}, {%4,%5,%6,%7}, {%8,%9}, {%0,%1,%2,%3};" \
        : "+f"((cc)[0]), "+f"((cc)[1]), "+f"((cc)[2]), "+f"((cc)[3]) \
        : "r"((aa)[0]), "r"((aa)[1]), "r"((aa)[2]), "r"((aa)[3]), \
          "r"(b0r), "r"(b1r))

// ---------------- converters ----------------
__global__ void k_cvtA(const float* __restrict__ A, unsigned* __restrict__ hi,
                       unsigned* __restrict__ lo, int MK2)
{
    int i = blockIdx.x * blockDim.x + threadIdx.x;
    if (i >= MK2) return;
    float2 v = *reinterpret_cast<const float2*>(A + (size_t)i * 2);
    unsigned h, l;
    packHL(v.x, v.y, h, l);
    hi[i] = h; lo[i] = l;
}

// all weights in one launch: Win, Wl, Wr, Wres
#define T_WIN (32 * 128)
#define T_WL  (NLAYERS * 64 * HCC)
#define T_WRS (3 * 64 * HIDD)
__global__ void k_cvtAll(
    const float* __restrict__ Win, const float* __restrict__ Wl,
    const float* __restrict__ Wr, const float* __restrict__ Wres,
    unsigned* __restrict__ WinH, unsigned* __restrict__ WinL,
    unsigned* __restrict__ WlH, unsigned* __restrict__ WlL,
    unsigned* __restrict__ WrH, unsigned* __restrict__ WrL,
    unsigned* __restrict__ WresH, unsigned* __restrict__ WresL)
{
    int i = blockIdx.x * blockDim.x + threadIdx.x;
    const float* B; unsigned *H, *L; int K2, N, idx;
    if (i < T_WIN)                     { B = Win;  H = WinH;  L = WinL;  K2 = 32; N = 128;  idx = i; }
    else if (i < T_WIN + T_WL)         { B = Wl;   H = WlH;   L = WlL;   K2 = 64; N = HCC;  idx = i - T_WIN; }
    else if (i < T_WIN + 2 * T_WL)     { B = Wr;   H = WrH;   L = WrL;   K2 = 64; N = HCC;  idx = i - T_WIN - T_WL; }
    else if (i < T_WIN + 2 * T_WL + T_WRS) { B = Wres; H = WresH; L = WresL; K2 = 64; N = HIDD; idx = i - T_WIN - 2 * T_WL; }
    else return;
    int n = idx % N;
    int r = idx / N;
    int k2 = r % K2;
    int b = r / K2;
    const float* base = B + (size_t)b * (2 * K2) * N;
    unsigned hh, ll;
    packHL(base[(size_t)(2 * k2) * N + n], base[(size_t)(2 * k2 + 1) * N + n], hh, ll);
    H[idx] = hh; L[idx] = ll;
}

// ---------------- CSR build ----------------
__global__ void k_zero() {
    int i = blockIdx.x * blockDim.x + threadIdx.x;
    if (i < NN) { g_deg[i] = 0; g_cur[i] = 0; }
    if (i < NG * HIDD) g_pool[i] = 0.f;
    if (i < NG) g_cnt[i] = 0.f;
}

__global__ void k_hist(const int* __restrict__ dst) {
    int e = blockIdx.x * blockDim.x + threadIdx.x;
    if (e < EE) atomicAdd(&g_deg[dst[e]], 1);
}

__global__ void k_scan() {
    __shared__ int sc[1024];
    int t = threadIdx.x;
    const int CH = 10;
    int base = t * CH;
    int loc[CH];
    int run = 0;
#pragma unroll
    for (int j = 0; j < CH; j++) {
        int idx = base + j;
        int v = (idx < NN) ? g_deg[idx] : 0;
        run += v; loc[j] = run;
    }
    sc[t] = run;
    __syncthreads();
    for (int d = 1; d < 1024; d <<= 1) {
        int v = (t >= d) ? sc[t - d] : 0;
        __syncthreads();
        sc[t] += v;
        __syncthreads();
    }
    int excl = (t > 0) ? sc[t - 1] : 0;
#pragma unroll
    for (int j = 0; j < CH; j++) {
        int idx = base + j;
        if (idx < NN) g_off[idx + 1] = excl + loc[j];
    }
    if (t == 0) g_off[0] = 0;
}

__global__ void k_scatter(const int* __restrict__ dst) {
    int e = blockIdx.x * blockDim.x + threadIdx.x;
    if (e < EE) {
        int d = dst[e];
        int p = atomicAdd(&g_cur[d], 1);
        g_csr[g_off[d] + p] = e;
    }
}

// ---------------- bf16x2 tensor GEMM: C = A @ B + bias (+ELU) (+packed output) ---------
template<int ACT, int PACK>
__global__ __launch_bounds__(256, 2) void k_gemm_bf(
    const unsigned* __restrict__ Ahi, const unsigned* __restrict__ Alo,
    const unsigned* __restrict__ Bhi, const unsigned* __restrict__ Blo,
    const float* __restrict__ bias, float* __restrict__ C,
    unsigned* __restrict__ Phi, unsigned* __restrict__ Plo,
    int M, int K2, int Nn)
{
    __shared__ __align__(16) unsigned AsH[2][128][12], AsL[2][128][12];
    __shared__ __align__(16) unsigned BsH[2][8][136], BsL[2][8][136];

    int tid = threadIdx.x;
    int lane = tid & 31, warp = tid >> 5;
    int g = lane >> 2, cq = lane & 3;
    int wm = (warp & 3) * 32;
    int wn = (warp >> 2) * 64;
    int m0 = blockIdx.x * 128, n0 = blockIdx.y * 128;

    int arow = tid >> 1;
    int af   = (tid & 1) * 4;
    int brow = tid >> 5;
    int bcol = (tid & 31) * 4;

    int rowA = m0 + arow;
    float c[2][8][4];
#pragma unroll
    for (int i = 0; i < 2; i++)
#pragma unroll
        for (int j = 0; j < 8; j++)
#pragma unroll
            for (int r = 0; r < 4; r++) c[i][j][r] = 0.f;

    int nt = K2 >> 3;

    uint4 ah, al, bh, bl;
    if (rowA < M) {
        ah = *(const uint4*)(Ahi + (size_t)rowA * K2 + af);
        al = *(const uint4*)(Alo + (size_t)rowA * K2 + af);
    } else { ah = make_uint4(0,0,0,0); al = ah; }
    bh = *(const uint4*)(Bhi + (size_t)brow * Nn + n0 + bcol);
    bl = *(const uint4*)(Blo + (size_t)brow * Nn + n0 + bcol);
    *(uint4*)&AsH[0][arow][af] = ah;
    *(uint4*)&AsL[0][arow][af] = al;
    *(uint4*)&BsH[0][brow][bcol] = bh;
    *(uint4*)&BsL[0][brow][bcol] = bl;
    __syncthreads();

    for (int t = 0; t < nt; t++) {
        int buf = t & 1;
        bool more = (t + 1 < nt);
        if (more) {
            int kt = (t + 1) * 8;
            if (rowA < M) {
                ah = *(const uint4*)(Ahi + (size_t)rowA * K2 + kt + af);
                al = *(const uint4*)(Alo + (size_t)rowA * K2 + kt + af);
            } else { ah = make_uint4(0,0,0,0); al = ah; }
            bh = *(const uint4*)(Bhi + (size_t)(kt + brow) * Nn + n0 + bcol);
            bl = *(const uint4*)(Blo + (size_t)(kt + brow) * Nn + n0 + bcol);
        }

        unsigned fah[2][4], fal[2][4];
#pragma unroll
        for (int i = 0; i < 2; i++) {
            int mr = wm + 16 * i + g;
            fah[i][0] = AsH[buf][mr][cq];     fah[i][1] = AsH[buf][mr + 8][cq];
            fah[i][2] = AsH[buf][mr][cq + 4]; fah[i][3] = AsH[buf][mr + 8][cq + 4];
            fal[i][0] = AsL[buf][mr][cq];     fal[i][1] = AsL[buf][mr + 8][cq];
            fal[i][2] = AsL[buf][mr][cq + 4]; fal[i][3] = AsL[buf][mr + 8][cq + 4];
        }
#pragma unroll
        for (int j = 0; j < 8; j++) {
            int nn = wn + 8 * j + g;
            unsigned bh0 = BsH[buf][cq][nn], bh1 = BsH[buf][cq + 4][nn];
            unsigned bl0 = BsL[buf][cq][nn], bl1 = BsL[buf][cq + 4][nn];
#pragma unroll
            for (int i = 0; i < 2; i++) {
                MMA_BF16(c[i][j], fah[i], bh0, bh1);
                MMA_BF16(c[i][j], fah[i], bl0, bl1);
                MMA_BF16(c[i][j], fal[i], bh0, bh1);
            }
        }
        __syncthreads();
        if (more) {
            int nb = buf ^ 1;
            *(uint4*)&AsH[nb][arow][af] = ah;
            *(uint4*)&AsL[nb][arow][af] = al;
            *(uint4*)&BsH[nb][brow][bcol] = bh;
            *(uint4*)&BsL[nb][brow][bcol] = bl;
            __syncthreads();
        }
    }

#pragma unroll
    for (int i = 0; i < 2; i++) {
        int r0 = m0 + wm + 16 * i + g;
#pragma unroll
        for (int j = 0; j < 8; j++) {
            int col = n0 + wn + 8 * j + 2 * cq;
            float bx = bias[col], by = bias[col + 1];
            float o0 = c[i][j][0] + bx, o1 = c[i][j][1] + by;
            float o2 = c[i][j][2] + bx, o3 = c[i][j][3] + by;
            if (ACT) { o0 = eluf(o0); o1 = eluf(o1); o2 = eluf(o2); o3 = eluf(o3); }
            if (r0 < M) {
                float2 st; st.x = o0; st.y = o1;
                *(float2*)(C + (size_t)r0 * Nn + col) = st;
                if (PACK) {
                    unsigned h, l;
                    packHL(o0, o1, h, l);
                    Phi[(size_t)r0 * (Nn / 2) + (col >> 1)] = h;
                    Plo[(size_t)r0 * (Nn / 2) + (col >> 1)] = l;
                }
            }
            if (r0 + 8 < M) {
                float2 st; st.x = o2; st.y = o3;
                *(float2*)(C + (size_t)(r0 + 8) * Nn + col) = st;
                if (PACK) {
                    unsigned h, l;
                    packHL(o2, o3, h, l);
                    Phi[(size_t)(r0 + 8) * (Nn / 2) + (col >> 1)] = h;
                    Plo[(size_t)(r0 + 8) * (Nn / 2) + (col >> 1)] = l;
                }
            }
        }
    }
}

// ---------------- fused GATv2 layer: logits + online softmax + aggregation +
// head-mean + bias + LayerNorm + ELU + residual + bf16 pack. ----------------
// 128 threads: warp = head, lane = 4 channels. NPB nodes per block (CSR order).
#define NPB 10
#define GCH 256

#define EACC(s, wk) { z.x += (s)*(wk).x; z.y += (s)*(wk).y; z.z += (s)*(wk).z; z.w += (s)*(wk).w; }

__global__ __launch_bounds__(128) void k_gat(
    const int* __restrict__ src,
    const float* __restrict__ xl, const float* __restrict__ xr,
    const float* __restrict__ ea, const float* __restrict__ We,
    const float* __restrict__ att,
    const float* __restrict__ b_gat, const float* __restrict__ gam,
    const float* __restrict__ bet, const float* __restrict__ resbuf,
    float* __restrict__ hout, unsigned* __restrict__ Phi, unsigned* __restrict__ Plo,
    int use_res)
{
    int t = threadIdx.x;
    int lane = t & 31, h = t >> 5;

    // per-block constants in registers (reused across ~NPB*deg edges)
    float4 w[ED];
#pragma unroll
    for (int k = 0; k < ED; k++)
        w[k] = *(const float4*)&We[k * HCC + h * 128 + lane * 4];
    float4 av = *(const float4*)&att[h * 128 + lane * 4];
    float bg = b_gat[t], gm = gam[t], bt = bet[t];

    __shared__ int    sS[GCH];
    __shared__ float4 sEa[GCH][4];
    __shared__ float  sOut[4][128];
    __shared__ float  red[128];
    __shared__ float  s_mu, s_rstd;

    int nEnd = min((blockIdx.x + 1) * NPB, NN);
    for (int node = blockIdx.x * NPB; node < nEnd; node++) {
        __syncthreads();   // protect smem reuse across nodes
        int lo = g_off[node];
        int deg = g_off[node + 1] - lo;
        float4 xrv = *(const float4*)&xr[(size_t)node * HCC + h * 128 + lane * 4];

        float M = -INFINITY, D = 0.f;
        float4 V = make_float4(0.f, 0.f, 0.f, 0.f);

        for (int base = 0; base < deg; base += GCH) {
            int cnt = min(GCH, deg - base);
            for (int k = t; k < cnt; k += 128)
                sS[k] = src[g_csr[lo + base + k]];
            for (int idx = t; idx < cnt * 4; idx += 128) {
                int e = g_csr[lo + base + (idx >> 2)];
                sEa[idx >> 2][idx & 3] =
                    ((const float4*)ea)[(size_t)e * 4 + (idx & 3)];
            }
            __syncthreads();

            // prefetch first xl row fragment
            float4 x = *(const float4*)(xl + (size_t)sS[0] * HCC + h * 128 + lane * 4);

            for (int k = 0; k < cnt; k++) {
                float4 xn = x;
                if (k + 1 < cnt)
                    xn = *(const float4*)(xl + (size_t)sS[k + 1] * HCC + h * 128 + lane * 4);
                float4 a0 = sEa[k][0], a1 = sEa[k][1], a2 = sEa[k][2], a3 = sEa[k][3];

                float4 z;
                z.x = x.x + xrv.x; z.y = x.y + xrv.y;
                z.z = x.z + xrv.z; z.w = x.w + xrv.w;
                EACC(a0.x, w[0])  EACC(a0.y, w[1])  EACC(a0.z, w[2])  EACC(a0.w, w[3])
                EACC(a1.x, w[4])  EACC(a1.y, w[5])  EACC(a1.z, w[6])  EACC(a1.w, w[7])
                EACC(a2.x, w[8])  EACC(a2.y, w[9])  EACC(a2.z, w[10]) EACC(a2.w, w[11])
                EACC(a3.x, w[12]) EACC(a3.y, w[13]) EACC(a3.z, w[14]) EACC(a3.w, w[15])

                float m0 = fmaxf(z.x, 0.2f * z.x);
                float m1 = fmaxf(z.y, 0.2f * z.y);
                float m2 = fmaxf(z.z, 0.2f * z.z);
                float m3 = fmaxf(z.w, 0.2f * z.w);
                float p = m0 * av.x + m1 * av.y + m2 * av.z + m3 * av.w;
#pragma unroll
                for (int off = 16; off > 0; off >>= 1)
                    p += __shfl_xor_sync(0xffffffffu, p, off);

                // online softmax update (uniform across warp)
                float Mn = fmaxf(M, p);
                float sc = __expf(M - Mn);     // exp(-inf)=0 on first edge
                float pe = __expf(p - Mn);
                D = D * sc + pe;
                V.x = V.x * sc + pe * x.x;
                V.y = V.y * sc + pe * x.y;
                V.z = V.z * sc + pe * x.z;
                V.w = V.w * sc + pe * x.w;
                M = Mn;
                x = xn;
            }
            __syncthreads();   // before next chunk overwrites sS/sEa
        }

        float dn = 1.f / (D + 1e-16f);
        sOut[h][lane * 4 + 0] = V.x * dn;
        sOut[h][lane * 4 + 1] = V.y * dn;
        sOut[h][lane * 4 + 2] = V.z * dn;
        sOut[h][lane * 4 + 3] = V.w * dn;
        __syncthreads();

        float gv = 0.25f * (sOut[0][t] + sOut[1][t] + sOut[2][t] + sOut[3][t]) + bg;

        // LayerNorm over 128 channels
        red[t] = gv; __syncthreads();
#pragma unroll
        for (int off = 64; off >= 1; off >>= 1) {
            if (t < off) red[t] += red[t + off];
            __syncthreads();
        }
        if (t == 0) s_mu = red[0] * (1.f / 128.f);
        __syncthreads();
        float dv = gv - s_mu;
        red[t] = dv * dv; __syncthreads();
#pragma unroll
        for (int off = 64; off >= 1; off >>= 1) {
            if (t < off) red[t] += red[t + off];
            __syncthreads();
        }
        if (t == 0) s_rstd = rsqrtf(red[0] * (1.f / 128.f) + 1e-5f);
        __syncthreads();

        float y = eluf(gm * dv * s_rstd + bt);
        if (use_res) y += resbuf[(size_t)node * HIDD + t];
        hout[(size_t)node * HIDD + t] = y;

        red[t] = y; __syncthreads();
        if (t < 64) {
            unsigned ph, pl;
            packHL(red[2 * t], red[2 * t + 1], ph, pl);
            Phi[(size_t)node * 64 + t] = ph;
            Plo[(size_t)node * 64 + t] = pl;
        }
    }
}

// ---------------- pooling + MLP head ----------------
__global__ void k_pool(const int* __restrict__ batch, const float* __restrict__ hsrc) {
    int i = blockIdx.x * blockDim.x + threadIdx.x;
    if (i >= NN * HIDD) return;
    int n = i >> 7, c = i & 127;
    int g = batch[n];
    atomicAdd(&g_pool[g * HIDD + c], hsrc[i]);
    if (c == 0) atomicAdd(&g_cnt[g], 1.0f);
}

__global__ __launch_bounds__(128) void k_mlp(
    const float* __restrict__ W1, const float* __restrict__ b1,
    const float* __restrict__ W2, const float* __restrict__ b2,
    const float* __restrict__ W3, const float* __restrict__ b3,
    float* __restrict__ out)
{
    int g = blockIdx.x, t = threadIdx.x;
    __shared__ float sh[128];
    __shared__ float s1[128];
    __shared__ float s2[64];
    __shared__ float red[64];

    float cnt = fmaxf(g_cnt[g], 1.0f);
    sh[t] = g_pool[g * HIDD + t] / cnt;
    __syncthreads();

    float acc = b1[t];
#pragma unroll 8
    for (int k = 0; k < 128; k++) acc += sh[k] * W1[k * 128 + t];
    s1[t] = fmaxf(acc, 0.f);
    __syncthreads();

    if (t < 64) {
        float a2 = b2[t];
#pragma unroll 8
        for (int k = 0; k < 128; k++) a2 += s1[k] * W2[k * 64 + t];
        s2[t] = fmaxf(a2, 0.f);
    }
    __syncthreads();
    if (t < 64) red[t] = s2[t] * W3[t];
    __syncthreads();
#pragma unroll
    for (int off = 32; off >= 1; off >>= 1) {
        if (t < off) red[t] += red[t + off];
        __syncthreads();
    }
    if (t == 0) out[g] = red[0] + b3[0];
}

// ---------------- host ----------------
extern "C" void kernel_launch(void* const* d_in, const int* in_sizes, int n_in,
                              void* d_out, int out_size)
{
    const float* x     = (const float*)d_in[0];
    const int*   ei    = (const int*)  d_in[1];
    const float* ea    = (const float*)d_in[2];
    const int*   batch = (const int*)  d_in[3];
    const float* Win   = (const float*)d_in[4];
    const float* b_in  = (const float*)d_in[5];
    const float* Wl    = (const float*)d_in[6];
    const float* bl    = (const float*)d_in[7];
    const float* Wr    = (const float*)d_in[8];
    const float* br    = (const float*)d_in[9];
    const float* We    = (const float*)d_in[10];
    const float* att   = (const float*)d_in[11];
    const float* b_gat = (const float*)d_in[12];
    const float* gam   = (const float*)d_in[13];
    const float* bet   = (const float*)d_in[14];
    const float* Wres  = (const float*)d_in[15];
    const float* bres  = (const float*)d_in[16];
    const float* W1    = (const float*)d_in[17];
    const float* b1    = (const float*)d_in[18];
    const float* W2    = (const float*)d_in[19];
    const float* b2    = (const float*)d_in[20];
    const float* W3    = (const float*)d_in[21];
    const float* b3    = (const float*)d_in[22];
    float* out = (float*)d_out;

    const int* src = ei;
    const int* dst = ei + EE;

    float *h0, *xl, *xr, *res;
    unsigned *PAh, *PAl, *PBh, *PBl;
    unsigned *WinH, *WinL, *WlH, *WlL, *WrH, *WrL, *WresH, *WresL;
    cudaGetSymbolAddress((void**)&h0,  g_h0);
    cudaGetSymbolAddress((void**)&xl,  g_xl);
    cudaGetSymbolAddress((void**)&xr,  g_xr);
    cudaGetSymbolAddress((void**)&res, g_res);
    cudaGetSymbolAddress((void**)&PAh, g_PAh);
    cudaGetSymbolAddress((void**)&PAl, g_PAl);
    cudaGetSymbolAddress((void**)&PBh, g_PBh);
    cudaGetSymbolAddress((void**)&PBl, g_PBl);
    cudaGetSymbolAddress((void**)&WinH, g_WinH);
    cudaGetSymbolAddress((void**)&WinL, g_WinL);
    cudaGetSymbolAddress((void**)&WlH, g_WlH);
    cudaGetSymbolAddress((void**)&WlL, g_WlL);
    cudaGetSymbolAddress((void**)&WrH, g_WrH);
    cudaGetSymbolAddress((void**)&WrL, g_WrL);
    cudaGetSymbolAddress((void**)&WresH, g_WresH);
    cudaGetSymbolAddress((void**)&WresL, g_WresL);

    dim3 gM128((NN + 127) / 128, 1);
    dim3 gHC((NN + 127) / 128, HCC / 128);

    // activation packed ping-pong: layer i GEMMs read P[(i+1)&1]; gat layer i writes P[i&1]
    unsigned* Ph[2] = { PAh, PBh };
    unsigned* Pl[2] = { PAl, PBl };

    const int CVT_TOTAL = T_WIN + 2 * T_WL + T_WRS;
    k_cvtAll<<<(CVT_TOTAL + 255) / 256, 256>>>(Win, Wl, Wr, Wres,
                                               WinH, WinL, WlH, WlL,
                                               WrH, WrL, WresH, WresL);           // 0
    k_cvtA<<<(NN * 32 + 255) / 256, 256>>>(x, PAh, PAl, NN * 32);                 // 1
    k_gemm_bf<1, 1><<<gM128, 256>>>(PAh, PAl, WinH, WinL, b_in, h0, PBh, PBl,
                                    NN, 32, HIDD);                                // 2
    k_gemm_bf<0, 0><<<gHC, 256>>>(PBh, PBl, WlH, WlL, bl, xl, 0, 0, NN, 64, HCC); // 3 (profiled)
    k_gemm_bf<0, 0><<<gHC, 256>>>(PBh, PBl, WrH, WrL, br, xr, 0, 0, NN, 64, HCC); // 4
    k_zero<<<(NG * HIDD + 255) / 256, 256>>>();
    k_hist<<<(EE + 255) / 256, 256>>>(dst);
    k_scan<<<1, 1024>>>();
    k_scatter<<<(EE + 255) / 256, 256>>>(dst);

    for (int i = 0; i < NLAYERS; i++) {
        int rd = (i + 1) & 1;
        if (i > 0) {
            k_gemm_bf<0, 0><<<gHC, 256>>>(Ph[rd], Pl[rd],
                                          WlH + (size_t)i * 64 * HCC, WlL + (size_t)i * 64 * HCC,
                                          bl + i * HCC, xl, 0, 0, NN, 64, HCC);
            k_gemm_bf<0, 0><<<gHC, 256>>>(Ph[rd], Pl[rd],
                                          WrH + (size_t)i * 64 * HCC, WrL + (size_t)i * 64 * HCC,
                                          br + i * HCC, xr, 0, 0, NN, 64, HCC);
            k_gemm_bf<0, 0><<<gM128, 256>>>(Ph[rd], Pl[rd],
                                            WresH + (size_t)(i - 1) * 64 * HIDD,
                                            WresL + (size_t)(i - 1) * 64 * HIDD,
                                            bres + (i - 1) * HIDD, res, 0, 0, NN, 64, HIDD);
        }
        k_gat<<<(NN + NPB - 1) / NPB, 128>>>(src, xl, xr, ea,
                                             We + (size_t)i * ED * HCC,
                                             att + (size_t)i * HCC,
                                             b_gat + i * HIDD, gam + i * HIDD, bet + i * HIDD,
                                             res, h0, Ph[i & 1], Pl[i & 1], (i > 0) ? 1 : 0);
    }

    k_pool<<<(NN * HIDD + 255) / 256, 256>>>(batch, h0);
    k_mlp<<<NG, 128>>>(W1, b1, W2, b2, W3, b3, out);
}

// round 11
// speedup vs baseline: 1.0954x; 1.0954x over previous
#include <cuda_runtime.h>
#include <cuda_bf16.h>
#include <math.h>

#define NN      10000
#define EE      100000
#define INC     64
#define ED      16
#define HIDD    128
#define NHEADS  4
#define HCC     512
#define NLAYERS 4
#define NG      256

// ---------------- scratch (device globals; no allocation allowed) ----------------
__device__ float g_h0[NN * HIDD];
__device__ float g_xl[NN * HCC];
__device__ float g_xr[NN * HCC];
__device__ float g_res[NN * HIDD];
__device__ int   g_deg[NN];
__device__ int   g_cur[NN];
__device__ int   g_off[NN + 1];
__device__ int   g_csr[EE];
__device__ float g_pool[NG * HIDD];
__device__ float g_cnt[NG];

// packed bf16x2 (hi/lo split) buffers: activations ping-pong + weights
__device__ unsigned g_PAh[NN * 64], g_PAl[NN * 64];
__device__ unsigned g_PBh[NN * 64], g_PBl[NN * 64];
__device__ unsigned g_WinH[32 * 128],          g_WinL[32 * 128];
__device__ unsigned g_WlH[NLAYERS * 64 * HCC], g_WlL[NLAYERS * 64 * HCC];
__device__ unsigned g_WrH[NLAYERS * 64 * HCC], g_WrL[NLAYERS * 64 * HCC];
__device__ unsigned g_WresH[3 * 64 * HIDD],    g_WresL[3 * 64 * HIDD];

__device__ __forceinline__ float eluf(float v) { return v > 0.f ? v : expm1f(v); }

__device__ __forceinline__ void packHL(float a, float b, unsigned& hi, unsigned& lo) {
    __nv_bfloat16 ha = __float2bfloat16(a);
    __nv_bfloat16 hb = __float2bfloat16(b);
    float la = a - __bfloat162float(ha);
    float lb = b - __bfloat162float(hb);
    __nv_bfloat16 lA = __float2bfloat16(la);
    __nv_bfloat16 lB = __float2bfloat16(lb);
    __nv_bfloat162 h2 = __halves2bfloat162(ha, hb);
    __nv_bfloat162 l2 = __halves2bfloat162(lA, lB);
    hi = *reinterpret_cast<unsigned*>(&h2);
    lo = *reinterpret_cast<unsigned*>(&l2);
}

#define MMA_BF16(cc, aa, b0r, b1r) \
    asm("mma.sync.aligned.m16n8k16.row.col.f32.bf16.bf16.f32 " \
        "{%0,%1,%2,%3}, {%4,%5,%6,%7}, {%8,%9}, {%0,%1,%2,%3};" \
        : "+f"((cc)[0]), "+f"((cc)[1]), "+f"((cc)[2]), "+f"((cc)[3]) \
        : "r"((aa)[0]), "r"((aa)[1]), "r"((aa)[2]), "r"((aa)[3]), \
          "r"(b0r), "r"(b1r))

// ---------------- converters ----------------
__global__ void k_cvtA(const float* __restrict__ A, unsigned* __restrict__ hi,
                       unsigned* __restrict__ lo, int MK2)
{
    int i = blockIdx.x * blockDim.x + threadIdx.x;
    if (i >= MK2) return;
    float2 v = *reinterpret_cast<const float2*>(A + (size_t)i * 2);
    unsigned h, l;
    packHL(v.x, v.y, h, l);
    hi[i] = h; lo[i] = l;
}

#define T_WIN (32 * 128)
#define T_WL  (NLAYERS * 64 * HCC)
#define T_WRS (3 * 64 * HIDD)
__global__ void k_cvtAll(
    const float* __restrict__ Win, const float* __restrict__ Wl,
    const float* __restrict__ Wr, const float* __restrict__ Wres,
    unsigned* __restrict__ WinH, unsigned* __restrict__ WinL,
    unsigned* __restrict__ WlH, unsigned* __restrict__ WlL,
    unsigned* __restrict__ WrH, unsigned* __restrict__ WrL,
    unsigned* __restrict__ WresH, unsigned* __restrict__ WresL)
{
    int i = blockIdx.x * blockDim.x + threadIdx.x;
    const float* B; unsigned *H, *L; int K2, N, idx;
    if (i < T_WIN)                     { B = Win;  H = WinH;  L = WinL;  K2 = 32; N = 128;  idx = i; }
    else if (i < T_WIN + T_WL)         { B = Wl;   H = WlH;   L = WlL;   K2 = 64; N = HCC;  idx = i - T_WIN; }
    else if (i < T_WIN + 2 * T_WL)     { B = Wr;   H = WrH;   L = WrL;   K2 = 64; N = HCC;  idx = i - T_WIN - T_WL; }
    else if (i < T_WIN + 2 * T_WL + T_WRS) { B = Wres; H = WresH; L = WresL; K2 = 64; N = HIDD; idx = i - T_WIN - 2 * T_WL; }
    else return;
    int n = idx % N;
    int r = idx / N;
    int k2 = r % K2;
    int b = r / K2;
    const float* base = B + (size_t)b * (2 * K2) * N;
    unsigned hh, ll;
    packHL(base[(size_t)(2 * k2) * N + n], base[(size_t)(2 * k2 + 1) * N + n], hh, ll);
    H[idx] = hh; L[idx] = ll;
}

// ---------------- CSR build ----------------
__global__ void k_zero() {
    int i = blockIdx.x * blockDim.x + threadIdx.x;
    if (i < NN) { g_deg[i] = 0; g_cur[i] = 0; }
    if (i < NG * HIDD) g_pool[i] = 0.f;
    if (i < NG) g_cnt[i] = 0.f;
}

__global__ void k_hist(const int* __restrict__ dst) {
    int e = blockIdx.x * blockDim.x + threadIdx.x;
    if (e < EE) atomicAdd(&g_deg[dst[e]], 1);
}

__global__ void k_scan() {
    __shared__ int sc[1024];
    int t = threadIdx.x;
    const int CH = 10;
    int base = t * CH;
    int loc[CH];
    int run = 0;
#pragma unroll
    for (int j = 0; j < CH; j++) {
        int idx = base + j;
        int v = (idx < NN) ? g_deg[idx] : 0;
        run += v; loc[j] = run;
    }
    sc[t] = run;
    __syncthreads();
    for (int d = 1; d < 1024; d <<= 1) {
        int v = (t >= d) ? sc[t - d] : 0;
        __syncthreads();
        sc[t] += v;
        __syncthreads();
    }
    int excl = (t > 0) ? sc[t - 1] : 0;
#pragma unroll
    for (int j = 0; j < CH; j++) {
        int idx = base + j;
        if (idx < NN) g_off[idx + 1] = excl + loc[j];
    }
    if (t == 0) g_off[0] = 0;
}

__global__ void k_scatter(const int* __restrict__ dst) {
    int e = blockIdx.x * blockDim.x + threadIdx.x;
    if (e < EE) {
        int d = dst[e];
        int p = atomicAdd(&g_cur[d], 1);
        g_csr[g_off[d] + p] = e;
    }
}

// ================= shared GEMM inner machinery (macro to keep one source of truth) ======
// Body expects: Ahi, Alo, Bhi, Blo, bias, C, M, K2, Nn, n0 defined; writes epilogue per flags.
#define GEMM_BODY(ACT, PACK, Phi, Plo)                                                     \
    __shared__ __align__(16) unsigned AsH[2][128][12], AsL[2][128][12];                    \
    __shared__ __align__(16) unsigned BsH[2][8][136], BsL[2][8][136];                      \
    int tid = threadIdx.x;                                                                 \
    int lane = tid & 31, warp = tid >> 5;                                                  \
    int g = lane >> 2, cq = lane & 3;                                                      \
    int wm = (warp & 3) * 32;                                                              \
    int wn = (warp >> 2) * 64;                                                             \
    int m0 = blockIdx.x * 128;                                                             \
    int arow = tid >> 1;                                                                   \
    int af   = (tid & 1) * 4;                                                              \
    int brow = tid >> 5;                                                                   \
    int bcol = (tid & 31) * 4;                                                             \
    int rowA = m0 + arow;                                                                  \
    float c[2][8][4];                                                                      \
    _Pragma("unroll") for (int i = 0; i < 2; i++)                                          \
    _Pragma("unroll") for (int j = 0; j < 8; j++)                                          \
    _Pragma("unroll") for (int r = 0; r < 4; r++) c[i][j][r] = 0.f;                        \
    int nt = K2 >> 3;                                                                      \
    uint4 ah, al, bh, bl;                                                                  \
    if (rowA < M) {                                                                        \
        ah = *(const uint4*)(Ahi + (size_t)rowA * K2 + af);                                \
        al = *(const uint4*)(Alo + (size_t)rowA * K2 + af);                                \
    } else { ah = make_uint4(0,0,0,0); al = ah; }                                          \
    bh = *(const uint4*)(Bhi + (size_t)brow * Nn + n0 + bcol);                             \
    bl = *(const uint4*)(Blo + (size_t)brow * Nn + n0 + bcol);                             \
    *(uint4*)&AsH[0][arow][af] = ah;                                                       \
    *(uint4*)&AsL[0][arow][af] = al;                                                       \
    *(uint4*)&BsH[0][brow][bcol] = bh;                                                     \
    *(uint4*)&BsL[0][brow][bcol] = bl;                                                     \
    __syncthreads();                                                                       \
    for (int t = 0; t < nt; t++) {                                                         \
        int buf = t & 1;                                                                   \
        bool more = (t + 1 < nt);                                                          \
        if (more) {                                                                        \
            int kt = (t + 1) * 8;                                                          \
            if (rowA < M) {                                                                \
                ah = *(const uint4*)(Ahi + (size_t)rowA * K2 + kt + af);                   \
                al = *(const uint4*)(Alo + (size_t)rowA * K2 + kt + af);                   \
            } else { ah = make_uint4(0,0,0,0); al = ah; }                                  \
            bh = *(const uint4*)(Bhi + (size_t)(kt + brow) * Nn + n0 + bcol);              \
            bl = *(const uint4*)(Blo + (size_t)(kt + brow) * Nn + n0 + bcol);              \
        }                                                                                  \
        unsigned fah[2][4], fal[2][4];                                                     \
        _Pragma("unroll") for (int i = 0; i < 2; i++) {                                    \
            int mr = wm + 16 * i + g;                                                      \
            fah[i][0] = AsH[buf][mr][cq];     fah[i][1] = AsH[buf][mr + 8][cq];            \
            fah[i][2] = AsH[buf][mr][cq + 4]; fah[i][3] = AsH[buf][mr + 8][cq + 4];        \
            fal[i][0] = AsL[buf][mr][cq];     fal[i][1] = AsL[buf][mr + 8][cq];            \
            fal[i][2] = AsL[buf][mr][cq + 4]; fal[i][3] = AsL[buf][mr + 8][cq + 4];        \
        }                                                                                  \
        _Pragma("unroll") for (int j = 0; j < 8; j++) {                                    \
            int nn = wn + 8 * j + g;                                                       \
            unsigned bh0 = BsH[buf][cq][nn], bh1 = BsH[buf][cq + 4][nn];                   \
            unsigned bl0 = BsL[buf][cq][nn], bl1 = BsL[buf][cq + 4][nn];                   \
            _Pragma("unroll") for (int i = 0; i < 2; i++) {                                \
                MMA_BF16(c[i][j], fah[i], bh0, bh1);                                       \
                MMA_BF16(c[i][j], fah[i], bl0, bl1);                                       \
                MMA_BF16(c[i][j], fal[i], bh0, bh1);                                       \
            }                                                                              \
        }                                                                                  \
        __syncthreads();                                                                   \
        if (more) {                                                                        \
            int nb = buf ^ 1;                                                              \
            *(uint4*)&AsH[nb][arow][af] = ah;                                              \
            *(uint4*)&AsL[nb][arow][af] = al;                                              \
            *(uint4*)&BsH[nb][brow][bcol] = bh;                                            \
            *(uint4*)&BsL[nb][brow][bcol] = bl;                                            \
            __syncthreads();                                                               \
        }                                                                                  \
    }                                                                                      \
    _Pragma("unroll") for (int i = 0; i < 2; i++) {                                        \
        int r0 = m0 + wm + 16 * i + g;                                                     \
        _Pragma("unroll") for (int j = 0; j < 8; j++) {                                    \
            int col = n0 + wn + 8 * j + 2 * cq;                                            \
            float bx = bias[col], by = bias[col + 1];                                      \
            float o0 = c[i][j][0] + bx, o1 = c[i][j][1] + by;                              \
            float o2 = c[i][j][2] + bx, o3 = c[i][j][3] + by;                              \
            if (ACT) { o0 = eluf(o0); o1 = eluf(o1); o2 = eluf(o2); o3 = eluf(o3); }       \
            if (r0 < M) {                                                                  \
                float2 st; st.x = o0; st.y = o1;                                           \
                *(float2*)(C + (size_t)r0 * Nn + col) = st;                                \
                if (PACK) {                                                                \
                    unsigned h, l;                                                         \
                    packHL(o0, o1, h, l);                                                  \
                    (Phi)[(size_t)r0 * (Nn / 2) + (col >> 1)] = h;                         \
                    (Plo)[(size_t)r0 * (Nn / 2) + (col >> 1)] = l;                         \
                }                                                                          \
            }                                                                              \
            if (r0 + 8 < M) {                                                              \
                float2 st; st.x = o2; st.y = o3;                                           \
                *(float2*)(C + (size_t)(r0 + 8) * Nn + col) = st;                          \
                if (PACK) {                                                                \
                    unsigned h, l;                                                         \
                    packHL(o2, o3, h, l);                                                  \
                    (Phi)[(size_t)(r0 + 8) * (Nn / 2) + (col >> 1)] = h;                   \
                    (Plo)[(size_t)(r0 + 8) * (Nn / 2) + (col >> 1)] = l;                   \
                }                                                                          \
            }                                                                              \
        }                                                                                  \
    }

// ---------------- input projection GEMM (ELU + packed output) ----------------
__global__ __launch_bounds__(256, 2) void k_gemm_in(
    const unsigned* __restrict__ Ahi, const unsigned* __restrict__ Alo,
    const unsigned* __restrict__ Bhi, const unsigned* __restrict__ Blo,
    const float* __restrict__ bias, float* __restrict__ C,
    unsigned* __restrict__ Phi, unsigned* __restrict__ Plo,
    int M, int K2, int Nn)
{
    int n0 = blockIdx.y * 128;
    GEMM_BODY(1, 1, Phi, Plo)
}

// ---------------- fused per-layer GEMM: one launch computes xl | xr | res -------------
// blockIdx.y: 0-3 -> Wl->xl, 4-7 -> Wr->xr, 8 -> Wres->res (if present). K=128 (K2=64).
__global__ __launch_bounds__(256, 2) void k_gemm_fused(
    const unsigned* __restrict__ Ahi, const unsigned* __restrict__ Alo,
    const unsigned* __restrict__ WlH_, const unsigned* __restrict__ WlL_,
    const unsigned* __restrict__ WrH_, const unsigned* __restrict__ WrL_,
    const unsigned* __restrict__ WresH_, const unsigned* __restrict__ WresL_,
    const float* __restrict__ blp, const float* __restrict__ brp,
    const float* __restrict__ bresp,
    float* __restrict__ xlp, float* __restrict__ xrp, float* __restrict__ resp,
    int M)
{
    const int K2 = 64;
    int yb = blockIdx.y;
    const unsigned *Bhi, *Blo;
    const float* bias;
    float* C;
    int Nn, n0;
    if (yb < 4)      { Bhi = WlH_;   Blo = WlL_;   bias = blp;   C = xlp;  Nn = HCC;  n0 = yb * 128; }
    else if (yb < 8) { Bhi = WrH_;   Blo = WrL_;   bias = brp;   C = xrp;  Nn = HCC;  n0 = (yb - 4) * 128; }
    else             { Bhi = WresH_; Blo = WresL_; bias = bresp; C = resp; Nn = HIDD; n0 = 0; }
    GEMM_BODY(0, 0, (unsigned*)0, (unsigned*)0)
}

// ---------------- fused GATv2 layer ----------------
#define NPB 10
#define GCH 256

#define EACC(s, wk) { z.x += (s)*(wk).x; z.y += (s)*(wk).y; z.z += (s)*(wk).z; z.w += (s)*(wk).w; }

__global__ __launch_bounds__(128) void k_gat(
    const int* __restrict__ src,
    const float* __restrict__ xl, const float* __restrict__ xr,
    const float* __restrict__ ea, const float* __restrict__ We,
    const float* __restrict__ att,
    const float* __restrict__ b_gat, const float* __restrict__ gam,
    const float* __restrict__ bet, const float* __restrict__ resbuf,
    float* __restrict__ hout, unsigned* __restrict__ Phi, unsigned* __restrict__ Plo,
    int use_res)
{
    int t = threadIdx.x;
    int lane = t & 31, h = t >> 5;

    float4 w[ED];
#pragma unroll
    for (int k = 0; k < ED; k++)
        w[k] = *(const float4*)&We[k * HCC + h * 128 + lane * 4];
    float4 av = *(const float4*)&att[h * 128 + lane * 4];
    float bg = b_gat[t], gm = gam[t], bt = bet[t];

    __shared__ int    sS[GCH];
    __shared__ float4 sEa[GCH][4];
    __shared__ float  sOut[4][128];
    __shared__ float  red[128];
    __shared__ float  s_mu, s_rstd;

    int nEnd = min((blockIdx.x + 1) * NPB, NN);
    for (int node = blockIdx.x * NPB; node < nEnd; node++) {
        __syncthreads();
        int lo = g_off[node];
        int deg = g_off[node + 1] - lo;
        float4 xrv = *(const float4*)&xr[(size_t)node * HCC + h * 128 + lane * 4];

        float M = -INFINITY, D = 0.f;
        float4 V = make_float4(0.f, 0.f, 0.f, 0.f);

        for (int base = 0; base < deg; base += GCH) {
            int cnt = min(GCH, deg - base);
            for (int k = t; k < cnt; k += 128)
                sS[k] = src[g_csr[lo + base + k]];
            for (int idx = t; idx < cnt * 4; idx += 128) {
                int e = g_csr[lo + base + (idx >> 2)];
                sEa[idx >> 2][idx & 3] =
                    ((const float4*)ea)[(size_t)e * 4 + (idx & 3)];
            }
            __syncthreads();

            float4 x = *(const float4*)(xl + (size_t)sS[0] * HCC + h * 128 + lane * 4);

            for (int k = 0; k < cnt; k++) {
                float4 xn = x;
                if (k + 1 < cnt)
                    xn = *(const float4*)(xl + (size_t)sS[k + 1] * HCC + h * 128 + lane * 4);
                float4 a0 = sEa[k][0], a1 = sEa[k][1], a2 = sEa[k][2], a3 = sEa[k][3];

                float4 z;
                z.x = x.x + xrv.x; z.y = x.y + xrv.y;
                z.z = x.z + xrv.z; z.w = x.w + xrv.w;
                EACC(a0.x, w[0])  EACC(a0.y, w[1])  EACC(a0.z, w[2])  EACC(a0.w, w[3])
                EACC(a1.x, w[4])  EACC(a1.y, w[5])  EACC(a1.z, w[6])  EACC(a1.w, w[7])
                EACC(a2.x, w[8])  EACC(a2.y, w[9])  EACC(a2.z, w[10]) EACC(a2.w, w[11])
                EACC(a3.x, w[12]) EACC(a3.y, w[13]) EACC(a3.z, w[14]) EACC(a3.w, w[15])

                float m0 = fmaxf(z.x, 0.2f * z.x);
                float m1 = fmaxf(z.y, 0.2f * z.y);
                float m2 = fmaxf(z.z, 0.2f * z.z);
                float m3 = fmaxf(z.w, 0.2f * z.w);
                float p = m0 * av.x + m1 * av.y + m2 * av.z + m3 * av.w;
#pragma unroll
                for (int off = 16; off > 0; off >>= 1)
                    p += __shfl_xor_sync(0xffffffffu, p, off);

                float Mn = fmaxf(M, p);
                float sc = __expf(M - Mn);
                float pe = __expf(p - Mn);
                D = D * sc + pe;
                V.x = V.x * sc + pe * x.x;
                V.y = V.y * sc + pe * x.y;
                V.z = V.z * sc + pe * x.z;
                V.w = V.w * sc + pe * x.w;
                M = Mn;
                x = xn;
            }
            __syncthreads();
        }

        float dn = 1.f / (D + 1e-16f);
        sOut[h][lane * 4 + 0] = V.x * dn;
        sOut[h][lane * 4 + 1] = V.y * dn;
        sOut[h][lane * 4 + 2] = V.z * dn;
        sOut[h][lane * 4 + 3] = V.w * dn;
        __syncthreads();

        float gv = 0.25f * (sOut[0][t] + sOut[1][t] + sOut[2][t] + sOut[3][t]) + bg;

        red[t] = gv; __syncthreads();
#pragma unroll
        for (int off = 64; off >= 1; off >>= 1) {
            if (t < off) red[t] += red[t + off];
            __syncthreads();
        }
        if (t == 0) s_mu = red[0] * (1.f / 128.f);
        __syncthreads();
        float dv = gv - s_mu;
        red[t] = dv * dv; __syncthreads();
#pragma unroll
        for (int off = 64; off >= 1; off >>= 1) {
            if (t < off) red[t] += red[t + off];
            __syncthreads();
        }
        if (t == 0) s_rstd = rsqrtf(red[0] * (1.f / 128.f) + 1e-5f);
        __syncthreads();

        float y = eluf(gm * dv * s_rstd + bt);
        if (use_res) y += resbuf[(size_t)node * HIDD + t];
        hout[(size_t)node * HIDD + t] = y;

        red[t] = y; __syncthreads();
        if (t < 64) {
            unsigned ph, pl;
            packHL(red[2 * t], red[2 * t + 1], ph, pl);
            Phi[(size_t)node * 64 + t] = ph;
            Plo[(size_t)node * 64 + t] = pl;
        }
    }
}

// ---------------- pooling + MLP head ----------------
__global__ void k_pool(const int* __restrict__ batch, const float* __restrict__ hsrc) {
    int i = blockIdx.x * blockDim.x + threadIdx.x;
    if (i >= NN * HIDD) return;
    int n = i >> 7, c = i & 127;
    int g = batch[n];
    atomicAdd(&g_pool[g * HIDD + c], hsrc[i]);
    if (c == 0) atomicAdd(&g_cnt[g], 1.0f);
}

__global__ __launch_bounds__(128) void k_mlp(
    const float* __restrict__ W1, const float* __restrict__ b1,
    const float* __restrict__ W2, const float* __restrict__ b2,
    const float* __restrict__ W3, const float* __restrict__ b3,
    float* __restrict__ out)
{
    int g = blockIdx.x, t = threadIdx.x;
    __shared__ float sh[128];
    __shared__ float s1[128];
    __shared__ float s2[64];
    __shared__ float red[64];

    float cnt = fmaxf(g_cnt[g], 1.0f);
    sh[t] = g_pool[g * HIDD + t] / cnt;
    __syncthreads();

    float acc = b1[t];
#pragma unroll 8
    for (int k = 0; k < 128; k++) acc += sh[k] * W1[k * 128 + t];
    s1[t] = fmaxf(acc, 0.f);
    __syncthreads();

    if (t < 64) {
        float a2 = b2[t];
#pragma unroll 8
        for (int k = 0; k < 128; k++) a2 += s1[k] * W2[k * 64 + t];
        s2[t] = fmaxf(a2, 0.f);
    }
    __syncthreads();
    if (t < 64) red[t] = s2[t] * W3[t];
    __syncthreads();
#pragma unroll
    for (int off = 32; off >= 1; off >>= 1) {
        if (t < off) red[t] += red[t + off];
        __syncthreads();
    }
    if (t == 0) out[g] = red[0] + b3[0];
}

// ---------------- host ----------------
extern "C" void kernel_launch(void* const* d_in, const int* in_sizes, int n_in,
                              void* d_out, int out_size)
{
    const float* x     = (const float*)d_in[0];
    const int*   ei    = (const int*)  d_in[1];
    const float* ea    = (const float*)d_in[2];
    const int*   batch = (const int*)  d_in[3];
    const float* Win   = (const float*)d_in[4];
    const float* b_in  = (const float*)d_in[5];
    const float* Wl    = (const float*)d_in[6];
    const float* bl    = (const float*)d_in[7];
    const float* Wr    = (const float*)d_in[8];
    const float* br    = (const float*)d_in[9];
    const float* We    = (const float*)d_in[10];
    const float* att   = (const float*)d_in[11];
    const float* b_gat = (const float*)d_in[12];
    const float* gam   = (const float*)d_in[13];
    const float* bet   = (const float*)d_in[14];
    const float* Wres  = (const float*)d_in[15];
    const float* bres  = (const float*)d_in[16];
    const float* W1    = (const float*)d_in[17];
    const float* b1    = (const float*)d_in[18];
    const float* W2    = (const float*)d_in[19];
    const float* b2    = (const float*)d_in[20];
    const float* W3    = (const float*)d_in[21];
    const float* b3    = (const float*)d_in[22];
    float* out = (float*)d_out;

    const int* src = ei;
    const int* dst = ei + EE;

    float *h0, *xl, *xr, *res;
    unsigned *PAh, *PAl, *PBh, *PBl;
    unsigned *WinH, *WinL, *WlH, *WlL, *WrH, *WrL, *WresH, *WresL;
    cudaGetSymbolAddress((void**)&h0,  g_h0);
    cudaGetSymbolAddress((void**)&xl,  g_xl);
    cudaGetSymbolAddress((void**)&xr,  g_xr);
    cudaGetSymbolAddress((void**)&res, g_res);
    cudaGetSymbolAddress((void**)&PAh, g_PAh);
    cudaGetSymbolAddress((void**)&PAl, g_PAl);
    cudaGetSymbolAddress((void**)&PBh, g_PBh);
    cudaGetSymbolAddress((void**)&PBl, g_PBl);
    cudaGetSymbolAddress((void**)&WinH, g_WinH);
    cudaGetSymbolAddress((void**)&WinL, g_WinL);
    cudaGetSymbolAddress((void**)&WlH, g_WlH);
    cudaGetSymbolAddress((void**)&WlL, g_WlL);
    cudaGetSymbolAddress((void**)&WrH, g_WrH);
    cudaGetSymbolAddress((void**)&WrL, g_WrL);
    cudaGetSymbolAddress((void**)&WresH, g_WresH);
    cudaGetSymbolAddress((void**)&WresL, g_WresL);

    dim3 gIn((NN + 127) / 128, 1);

    unsigned* Ph[2] = { PAh, PBh };
    unsigned* Pl[2] = { PAl, PBl };

    const int CVT_TOTAL = T_WIN + 2 * T_WL + T_WRS;
    k_cvtAll<<<(CVT_TOTAL + 255) / 256, 256>>>(Win, Wl, Wr, Wres,
                                               WinH, WinL, WlH, WlL,
                                               WrH, WrL, WresH, WresL);            // 0
    k_cvtA<<<(NN * 32 + 255) / 256, 256>>>(x, PAh, PAl, NN * 32);                  // 1
    k_gemm_in<<<gIn, 256>>>(PAh, PAl, WinH, WinL, b_in, h0, PBh, PBl,
                            NN, 32, HIDD);                                         // 2
    // layer 0 fused GEMM (no res): blockIdx.y in [0,8)
    {
        dim3 g((NN + 127) / 128, 8);
        k_gemm_fused<<<g, 256>>>(PBh, PBl, WlH, WlL, WrH, WrL,
                                 WresH, WresL, bl, br, bres,
                                 xl, xr, res, NN);                                 // 3 (profiled?)
    }
    k_zero<<<(NG * HIDD + 255) / 256, 256>>>();                                    // 4
    k_hist<<<(EE + 255) / 256, 256>>>(dst);                                        // 5
    k_scan<<<1, 1024>>>();
    k_scatter<<<(EE + 255) / 256, 256>>>(dst);

    for (int i = 0; i < NLAYERS; i++) {
        if (i > 0) {
            int rd = (i + 1) & 1;
            dim3 g((NN + 127) / 128, 9);
            k_gemm_fused<<<g, 256>>>(Ph[rd], Pl[rd],
                                     WlH + (size_t)i * 64 * HCC, WlL + (size_t)i * 64 * HCC,
                                     WrH + (size_t)i * 64 * HCC, WrL + (size_t)i * 64 * HCC,
                                     WresH + (size_t)(i - 1) * 64 * HIDD,
                                     WresL + (size_t)(i - 1) * 64 * HIDD,
                                     bl + i * HCC, br + i * HCC, bres + (i - 1) * HIDD,
                                     xl, xr, res, NN);
        }
        k_gat<<<(NN + NPB - 1) / NPB, 128>>>(src, xl, xr, ea,
                                             We + (size_t)i * ED * HCC,
                                             att + (size_t)i * HCC,
                                             b_gat + i * HIDD, gam + i * HIDD, bet + i * HIDD,
                                             res, h0, Ph[i & 1], Pl[i & 1], (i > 0) ? 1 : 0);
    }

    k_pool<<<(NN * HIDD + 255) / 256, 256>>>(batch, h0);
    k_mlp<<<NG, 128>>>(W1, b1, W2, b2, W3, b3, out);
}